// round 1
// baseline (speedup 1.0000x reference)
#include <cuda_runtime.h>

// ---------------------------------------------------------------------------
// MSE + SSIM loss, 32x1x512x512 fp32 -> scalar.
//   loss = 0.6 * mean((p-t)^2) + 0.4 * (1 - mean(ssim_map))
// ssim uses 11x11 Gaussian (sigma=1.5) VALID conv -> 502x502 map per image.
// Gaussian is separable: horizontal then vertical 11-tap passes, fully fused
// in shared memory (5 blurred fields never touch HBM).
// ---------------------------------------------------------------------------

#define H 512
#define W 512
#define B 32
#define OV 502            // valid output size (512 - 11 + 1)
#define TO 32             // output tile (square)
#define TI 42             // input tile = TO + 10
#define PAD 43            // smem row stride for input tiles (odd -> conflict-free)
#define HP 33             // smem row stride for hconv buffer

__device__ double g_accum[2];   // [0] = mse sum, [1] = ssim sum

__global__ void init_kernel() {
    g_accum[0] = 0.0;
    g_accum[1] = 0.0;
}

// ---------------------------------------------------------------------------
__global__ __launch_bounds__(256) void mse_kernel(
    const float4* __restrict__ p, const float4* __restrict__ t, int n4)
{
    float s = 0.0f;
    int idx = blockIdx.x * blockDim.x + threadIdx.x;
    int stride = gridDim.x * blockDim.x;
    for (int i = idx; i < n4; i += stride) {
        float4 a = p[i];
        float4 b = t[i];
        float d0 = a.x - b.x, d1 = a.y - b.y, d2 = a.z - b.z, d3 = a.w - b.w;
        s += d0 * d0 + d1 * d1 + d2 * d2 + d3 * d3;
    }
    #pragma unroll
    for (int o = 16; o; o >>= 1) s += __shfl_down_sync(0xffffffffu, s, o);
    __shared__ float ws[8];
    int lane = threadIdx.x & 31, wid = threadIdx.x >> 5;
    if (!lane) ws[wid] = s;
    __syncthreads();
    if (wid == 0) {
        s = (lane < 8) ? ws[lane] : 0.0f;
        #pragma unroll
        for (int o = 4; o; o >>= 1) s += __shfl_down_sync(0xffffffffu, s, o);
        if (!lane) atomicAdd(&g_accum[0], (double)s);
    }
}

// ---------------------------------------------------------------------------
// One block per 32x32 output tile. 256 threads.
__global__ __launch_bounds__(256) void ssim_kernel(
    const float* __restrict__ pred, const float* __restrict__ targ)
{
    __shared__ float sp[TI][PAD];
    __shared__ float st[TI][PAD];
    __shared__ float hb[5][TI][HP];
    __shared__ float gwsh[11];
    __shared__ float ws[8];

    const int tid = threadIdx.x;

    // Gaussian weights (match reference: exp(-d^2/(2*1.5^2)) normalized)
    if (tid == 0) {
        float e[11];
        float sum = 0.0f;
        #pragma unroll
        for (int k = 0; k < 11; k++) {
            float d = (float)k - 5.0f;
            e[k] = expf(-d * d / 4.5f);
            sum += e[k];
        }
        #pragma unroll
        for (int k = 0; k < 11; k++) gwsh[k] = e[k] / sum;
    }
    __syncthreads();
    float g[11];
    #pragma unroll
    for (int k = 0; k < 11; k++) g[k] = gwsh[k];

    const int r0 = blockIdx.y * TO;
    const int c0 = blockIdx.x * TO;
    const float* pim = pred + (size_t)blockIdx.z * (H * W);
    const float* tim = targ + (size_t)blockIdx.z * (H * W);

    // Load 42x42 halo tiles (clamped; clamped values feed only invalid outputs)
    for (int i = tid; i < TI * TI; i += 256) {
        int r = i / TI, c = i % TI;
        int gr = min(r0 + r, H - 1);
        int gc = min(c0 + c, W - 1);
        sp[r][c] = pim[gr * W + gc];
        st[r][c] = tim[gr * W + gc];
    }
    __syncthreads();

    // Horizontal 11-tap conv of 5 fields: 42 rows x 8 groups of 4 cols = 336 tasks
    for (int task = tid; task < TI * 8; task += 256) {
        int row = task >> 3;
        int cg = (task & 7) << 2;
        float pv[14], tv[14], pp[14], tt[14], pt[14];
        #pragma unroll
        for (int k = 0; k < 14; k++) {
            float p = sp[row][cg + k];
            float t = st[row][cg + k];
            pv[k] = p; tv[k] = t;
            pp[k] = p * p; tt[k] = t * t; pt[k] = p * t;
        }
        #pragma unroll
        for (int j = 0; j < 4; j++) {
            float a0 = 0.f, a1 = 0.f, a2 = 0.f, a3 = 0.f, a4 = 0.f;
            #pragma unroll
            for (int k = 0; k < 11; k++) {
                float w = g[k];
                a0 += w * pv[j + k];
                a1 += w * tv[j + k];
                a2 += w * pp[j + k];
                a3 += w * tt[j + k];
                a4 += w * pt[j + k];
            }
            hb[0][row][cg + j] = a0;
            hb[1][row][cg + j] = a1;
            hb[2][row][cg + j] = a2;
            hb[3][row][cg + j] = a3;
            hb[4][row][cg + j] = a4;
        }
    }
    __syncthreads();

    // Vertical 11-tap conv + SSIM: 32 cols x 8 row-groups of 4 = 256 tasks
    float lsum = 0.0f;
    {
        const int c = tid & 31;
        const int rbase = (tid >> 5) << 2;
        float v0[14], v1[14], v2[14], v3[14], v4[14];
        #pragma unroll
        for (int k = 0; k < 14; k++) {
            v0[k] = hb[0][rbase + k][c];
            v1[k] = hb[1][rbase + k][c];
            v2[k] = hb[2][rbase + k][c];
            v3[k] = hb[3][rbase + k][c];
            v4[k] = hb[4][rbase + k][c];
        }
        const float C1 = 1e-4f, C2 = 9e-4f;
        #pragma unroll
        for (int j = 0; j < 4; j++) {
            float mu1 = 0.f, mu2 = 0.f, bpp = 0.f, btt = 0.f, bpt = 0.f;
            #pragma unroll
            for (int k = 0; k < 11; k++) {
                float w = g[k];
                mu1 += w * v0[j + k];
                mu2 += w * v1[j + k];
                bpp += w * v2[j + k];
                btt += w * v3[j + k];
                bpt += w * v4[j + k];
            }
            int orow = r0 + rbase + j;
            int ocol = c0 + c;
            if (orow < OV && ocol < OV) {
                float mu1sq = mu1 * mu1;
                float mu2sq = mu2 * mu2;
                float mu12  = mu1 * mu2;
                float s1 = bpp - mu1sq;
                float s2 = btt - mu2sq;
                float s12 = bpt - mu12;
                float num = (2.0f * mu12 + C1) * (2.0f * s12 + C2);
                float den = (mu1sq + mu2sq + C1) * (s1 + s2 + C2) + 1e-6f;
                lsum += num / den;
            }
        }
    }

    // Block reduce ssim partial sum
    #pragma unroll
    for (int o = 16; o; o >>= 1) lsum += __shfl_down_sync(0xffffffffu, lsum, o);
    int lane = tid & 31, wid = tid >> 5;
    if (!lane) ws[wid] = lsum;
    __syncthreads();
    if (wid == 0) {
        lsum = (lane < 8) ? ws[lane] : 0.0f;
        #pragma unroll
        for (int o = 4; o; o >>= 1) lsum += __shfl_down_sync(0xffffffffu, lsum, o);
        if (!lane) atomicAdd(&g_accum[1], (double)lsum);
    }
}

// ---------------------------------------------------------------------------
__global__ void finalize_kernel(float* __restrict__ out) {
    double mse = g_accum[0] / ((double)B * H * W);
    double smean = g_accum[1] / ((double)B * OV * OV);
    out[0] = (float)(0.6 * mse + 0.4 * (1.0 - smean));
}

// ---------------------------------------------------------------------------
extern "C" void kernel_launch(void* const* d_in, const int* in_sizes, int n_in,
                              void* d_out, int out_size)
{
    const float* pred = (const float*)d_in[0];
    const float* targ = (const float*)d_in[1];

    init_kernel<<<1, 1>>>();

    int n4 = (B * H * W) / 4;
    mse_kernel<<<2048, 256>>>((const float4*)pred, (const float4*)targ, n4);

    dim3 grid((OV + TO - 1) / TO, (OV + TO - 1) / TO, B);   // 16 x 16 x 32
    ssim_kernel<<<grid, 256>>>(pred, targ);

    finalize_kernel<<<1, 1>>>((float*)d_out);
}

// round 4
// speedup vs baseline: 1.4598x; 1.4598x over previous
#include <cuda_runtime.h>

// ---------------------------------------------------------------------------
// Fully fused MSE + SSIM loss, 32x1x512x512 fp32 -> scalar. ONE kernel.
//   loss = 0.6 * mean((p-t)^2) + 0.4 * (1 - mean(ssim_map))
// 11x11 Gaussian separable blur of 4 fields: p, t, p^2+t^2, p*t.
// Weights are compile-time literals -> FFMA-imm (rt=1, 2x fp32 issue rate).
// MSE computed from the same smem tiles (each pixel owned by one tile).
// Last-block-done epilogue computes the scalar (no init/finalize kernels).
// ---------------------------------------------------------------------------

#define H 512
#define W 512
#define B 32
#define OV 502            // valid output size (512 - 11 + 1)
#define TO 32             // output tile (square)
#define TI 42             // input tile = TO + 10
#define PADI 44           // smem row stride (multiple of 4 -> float4 aligned)
#define HBW 32            // hconv buffer row width
#define NBLOCKS (16 * 16 * 32)

// 11-tap Gaussian, sigma=1.5, normalized (matches reference to ~1e-7).
// Function-local constexpr (file-scope constexpr is not visible in device
// code without --expt-relaxed-constexpr). All indices are compile-time under
// #pragma unroll, so each tap becomes an FFMA immediate operand.
#define DECLARE_GW                                                            \
    constexpr float GW[11] = {                                                \
        0.00102838f, 0.00759875f, 0.03600077f, 0.10936080f, 0.21300549f,      \
        0.26601166f,                                                          \
        0.21300549f, 0.10936080f, 0.03600077f, 0.00759875f, 0.00102838f };

__device__ double g_accum[2] = {0.0, 0.0};   // [0]=mse sum, [1]=ssim sum
__device__ unsigned int g_count = 0;

__global__ __launch_bounds__(256) void fused_kernel(
    const float* __restrict__ pred, const float* __restrict__ targ,
    float* __restrict__ out)
{
    DECLARE_GW

    __shared__ __align__(16) float sp[TI][PADI];
    __shared__ __align__(16) float st[TI][PADI];
    __shared__ __align__(16) float hb[4][TI][HBW];
    __shared__ float ws[2][8];

    const int tid = threadIdx.x;
    const int r0 = blockIdx.y * TO;
    const int c0 = blockIdx.x * TO;
    const float* pim = pred + (size_t)blockIdx.z * (H * W);
    const float* tim = targ + (size_t)blockIdx.z * (H * W);

    // ---- load 42x42 halo tiles (clamped values only feed invalid outputs)
    for (int i = tid; i < TI * TI; i += 256) {
        int r = i / TI, c = i - r * TI;
        int gr = min(r0 + r, H - 1);
        int gc = min(c0 + c, W - 1);
        sp[r][c] = pim[gr * W + gc];
        st[r][c] = tim[gr * W + gc];
    }
    __syncthreads();

    // ---- MSE over the owned 32x32 interior (tiles partition the image)
    float msum = 0.0f;
    #pragma unroll
    for (int q = 0; q < 4; q++) {
        int p = tid + 256 * q;
        int r = p >> 5, c = p & 31;
        float d = sp[r][c] - st[r][c];
        msum = fmaf(d, d, msum);
    }

    // ---- horizontal 11-tap conv of 4 fields: 42 rows x 8 col-groups of 4
    for (int task = tid; task < TI * 8; task += 256) {
        int row = task >> 3;
        int cg = (task & 7) << 2;

        float pw[16], tw[16];
        #pragma unroll
        for (int q = 0; q < 4; q++) {
            float4 v = *(const float4*)&sp[row][cg + 4 * q];
            pw[4 * q + 0] = v.x; pw[4 * q + 1] = v.y;
            pw[4 * q + 2] = v.z; pw[4 * q + 3] = v.w;
            float4 u = *(const float4*)&st[row][cg + 4 * q];
            tw[4 * q + 0] = u.x; tw[4 * q + 1] = u.y;
            tw[4 * q + 2] = u.z; tw[4 * q + 3] = u.w;
        }

        #define HCONV(win, dst)                                              \
        {                                                                    \
            float a0 = 0.f, a1 = 0.f, a2 = 0.f, a3 = 0.f;                    \
            _Pragma("unroll")                                                \
            for (int k = 0; k < 11; k++) {                                   \
                a0 = fmaf(win[k + 0], GW[k], a0);                            \
                a1 = fmaf(win[k + 1], GW[k], a1);                            \
                a2 = fmaf(win[k + 2], GW[k], a2);                            \
                a3 = fmaf(win[k + 3], GW[k], a3);                            \
            }                                                                \
            *(float4*)&dst[row][cg] = make_float4(a0, a1, a2, a3);           \
        }

        HCONV(pw, hb[0]);          // mu1 (horizontal)
        HCONV(tw, hb[1]);          // mu2 (horizontal)
        #pragma unroll
        for (int k = 0; k < 14; k++) {       // overwrite windows with p^2+t^2, p*t
            float p = pw[k], t = tw[k];
            pw[k] = fmaf(p, p, t * t);
            tw[k] = p * t;
        }
        HCONV(pw, hb[2]);          // blur(p^2 + t^2) (horizontal)
        HCONV(tw, hb[3]);          // blur(p*t)       (horizontal)
        #undef HCONV
    }
    __syncthreads();

    // ---- vertical 11-tap conv + SSIM: 32 cols x 8 row-groups of 4
    float lsum = 0.0f;
    {
        const int c = tid & 31;
        const int rb = (tid >> 5) << 2;
        float mu1[4], mu2[4], bs[4], bpt[4];

        #define VCONV(f, dst)                                                \
        {                                                                    \
            float win[14];                                                   \
            _Pragma("unroll")                                                \
            for (int k = 0; k < 14; k++) win[k] = hb[f][rb + k][c];          \
            dst[0] = dst[1] = dst[2] = dst[3] = 0.f;                         \
            _Pragma("unroll")                                                \
            for (int k = 0; k < 11; k++) {                                   \
                dst[0] = fmaf(win[k + 0], GW[k], dst[0]);                    \
                dst[1] = fmaf(win[k + 1], GW[k], dst[1]);                    \
                dst[2] = fmaf(win[k + 2], GW[k], dst[2]);                    \
                dst[3] = fmaf(win[k + 3], GW[k], dst[3]);                    \
            }                                                                \
        }
        VCONV(0, mu1)
        VCONV(1, mu2)
        VCONV(2, bs)
        VCONV(3, bpt)
        #undef VCONV

        const float C1 = 1e-4f, C2 = 9e-4f;
        #pragma unroll
        for (int j = 0; j < 4; j++) {
            int orow = r0 + rb + j;
            int ocol = c0 + c;
            if (orow < OV && ocol < OV) {
                float m1 = mu1[j], m2 = mu2[j];
                float m1s = m1 * m1, m2s = m2 * m2, m12 = m1 * m2;
                float musum = m1s + m2s;
                float sigsum = bs[j] - musum;          // sigma1^2 + sigma2^2
                float s12 = bpt[j] - m12;              // sigma12
                float num = (2.0f * m12 + C1) * (2.0f * s12 + C2);
                float den = (musum + C1) * (sigsum + C2) + 1e-6f;
                lsum += num / den;
            }
        }
    }

    // ---- block reduction of (msum, lsum)
    #pragma unroll
    for (int o = 16; o; o >>= 1) {
        msum += __shfl_down_sync(0xffffffffu, msum, o);
        lsum += __shfl_down_sync(0xffffffffu, lsum, o);
    }
    int lane = tid & 31, wid = tid >> 5;
    if (!lane) { ws[0][wid] = msum; ws[1][wid] = lsum; }
    __syncthreads();
    if (wid == 0) {
        msum = (lane < 8) ? ws[0][lane] : 0.0f;
        lsum = (lane < 8) ? ws[1][lane] : 0.0f;
        #pragma unroll
        for (int o = 4; o; o >>= 1) {
            msum += __shfl_down_sync(0xffffffffu, msum, o);
            lsum += __shfl_down_sync(0xffffffffu, lsum, o);
        }
        if (!lane) {
            atomicAdd(&g_accum[0], (double)msum);
            atomicAdd(&g_accum[1], (double)lsum);
            __threadfence();
            unsigned done = atomicAdd(&g_count, 1u);
            if (done == NBLOCKS - 1) {
                // last block: counter==NBLOCKS-1 implies every block's fence
                // has executed, so all g_accum atomics are visible. Read them
                // back with atomic adds of 0 (L2-coherent read-modify-write).
                double a0 = atomicAdd(&g_accum[0], 0.0);
                double a1 = atomicAdd(&g_accum[1], 0.0);
                double mse = a0 / (double)(B * H * W);
                double smean = a1 / ((double)B * OV * OV);
                out[0] = (float)(0.6 * mse + 0.4 * (1.0 - smean));
                // reset for next (graph-replayed) launch; replays are
                // serialized, so these plain stores are safe.
                g_accum[0] = 0.0;
                g_accum[1] = 0.0;
                g_count = 0u;
            }
        }
    }
}

// ---------------------------------------------------------------------------
extern "C" void kernel_launch(void* const* d_in, const int* in_sizes, int n_in,
                              void* d_out, int out_size)
{
    const float* pred = (const float*)d_in[0];
    const float* targ = (const float*)d_in[1];

    dim3 grid((OV + TO - 1) / TO, (OV + TO - 1) / TO, B);   // 16 x 16 x 32
    fused_kernel<<<grid, 256>>>(pred, targ, (float*)d_out);
}

// round 5
// speedup vs baseline: 1.6494x; 1.1299x over previous
#include <cuda_runtime.h>

// ---------------------------------------------------------------------------
// Fully fused MSE + SSIM loss, 32x1x512x512 fp32 -> scalar. ONE kernel.
// Round-5 change: all four 11-tap blur fields run as TWO packed f32x2 chains
// (fma.rn.f32x2 = 2 FMAs/issue slot, PTX-only on sm_103a). pred/target live
// interleaved (p,t) in smem so packing is free; hconv output is float2 so
// vconv does LDS.64 (half the loads + half the address ALU of round 4).
// ---------------------------------------------------------------------------

#define H 512
#define W 512
#define B 32
#define OV 502            // valid output size (512 - 11 + 1)
#define TO 32             // output tile (square)
#define TI 42             // input tile = TO + 10
#define PADI 44           // smem row stride in float2 elements
#define HBW 32            // hconv buffer row width (float2 elements)
#define NBLOCKS (16 * 16 * 32)

typedef unsigned long long u64;

__device__ __forceinline__ u64 pk2(float lo, float hi) {
    u64 r; asm("mov.b64 %0, {%1, %2};" : "=l"(r) : "f"(lo), "f"(hi)); return r;
}
__device__ __forceinline__ void upk2(u64 v, float& lo, float& hi) {
    asm("mov.b64 {%0, %1}, %2;" : "=f"(lo), "=f"(hi) : "l"(v));
}
__device__ __forceinline__ u64 ffma2(u64 a, u64 w, u64 c) {
    u64 d; asm("fma.rn.f32x2 %0, %1, %2, %3;" : "=l"(d) : "l"(a), "l"(w), "l"(c));
    return d;
}

// 11-tap Gaussian, sigma=1.5, normalized; symmetric -> 6 distinct values.
#define GW0 0.00102838f
#define GW1 0.00759875f
#define GW2 0.03600077f
#define GW3 0.10936080f
#define GW4 0.21300549f
#define GW5 0.26601166f

#define DECLARE_W2                                                            \
    const u64 W2[11] = {                                                      \
        pk2(GW0, GW0), pk2(GW1, GW1), pk2(GW2, GW2), pk2(GW3, GW3),           \
        pk2(GW4, GW4), pk2(GW5, GW5),                                         \
        pk2(GW4, GW4), pk2(GW3, GW3), pk2(GW2, GW2), pk2(GW1, GW1),           \
        pk2(GW0, GW0) };

__device__ double g_accum[2] = {0.0, 0.0};   // [0]=mse sum, [1]=ssim sum
__device__ unsigned int g_count = 0;

__global__ __launch_bounds__(256) void fused_kernel(
    const float* __restrict__ pred, const float* __restrict__ targ,
    float* __restrict__ out)
{
    // (p,t) interleaved input tile and 2 packed-field-pair hconv buffers
    __shared__ __align__(16) u64 s2[TI][PADI];
    __shared__ __align__(16) u64 hb2[2][TI][HBW];
    __shared__ float ws[2][8];

    const int tid = threadIdx.x;
    const int r0 = blockIdx.y * TO;
    const int c0 = blockIdx.x * TO;
    const float* pim = pred + (size_t)blockIdx.z * (H * W);
    const float* tim = targ + (size_t)blockIdx.z * (H * W);

    // ---- load 42x42 halo tile, interleaved (p,t) per pixel
    #pragma unroll
    for (int q = 0; q < 7; q++) {
        int i = tid + 256 * q;
        if (i < TI * TI) {
            int r = i / TI, c = i - r * TI;
            int gr = min(r0 + r, H - 1);
            int gc = min(c0 + c, W - 1);
            int gidx = gr * W + gc;
            s2[r][c] = pk2(pim[gidx], tim[gidx]);
        }
    }
    __syncthreads();

    // ---- MSE over the owned 32x32 interior (tiles partition the image)
    float msum = 0.0f;
    #pragma unroll
    for (int q = 0; q < 4; q++) {
        int p = tid + 256 * q;
        float pv, tv;
        upk2(s2[p >> 5][p & 31], pv, tv);
        float d = pv - tv;
        msum = fmaf(d, d, msum);
    }

    // ---- horizontal 11-tap conv, 2 packed chains: 42 rows x 8 groups of 4
    {
        DECLARE_W2
        for (int task = tid; task < TI * 8; task += 256) {
            int row = task >> 3;
            int cg = (task & 7) << 2;

            u64 win[14];
            #pragma unroll
            for (int q = 0; q < 7; q++) {
                ulonglong2 v = *(const ulonglong2*)&s2[row][cg + 2 * q];
                win[2 * q + 0] = v.x;
                win[2 * q + 1] = v.y;
            }

            // chain A: (blur_h(p), blur_h(t))
            {
                u64 a0 = 0, a1 = 0, a2 = 0, a3 = 0;
                #pragma unroll
                for (int k = 0; k < 11; k++) {
                    a0 = ffma2(win[k + 0], W2[k], a0);
                    a1 = ffma2(win[k + 1], W2[k], a1);
                    a2 = ffma2(win[k + 2], W2[k], a2);
                    a3 = ffma2(win[k + 3], W2[k], a3);
                }
                *(ulonglong2*)&hb2[0][row][cg + 0] = make_ulonglong2(a0, a1);
                *(ulonglong2*)&hb2[0][row][cg + 2] = make_ulonglong2(a2, a3);
            }
            // transform windows in place: (p,t) -> (p^2 + t^2, p*t)
            #pragma unroll
            for (int k = 0; k < 14; k++) {
                float p, t;
                upk2(win[k], p, t);
                win[k] = pk2(fmaf(p, p, t * t), p * t);
            }
            // chain B: (blur_h(p^2+t^2), blur_h(p*t))
            {
                u64 a0 = 0, a1 = 0, a2 = 0, a3 = 0;
                #pragma unroll
                for (int k = 0; k < 11; k++) {
                    a0 = ffma2(win[k + 0], W2[k], a0);
                    a1 = ffma2(win[k + 1], W2[k], a1);
                    a2 = ffma2(win[k + 2], W2[k], a2);
                    a3 = ffma2(win[k + 3], W2[k], a3);
                }
                *(ulonglong2*)&hb2[1][row][cg + 0] = make_ulonglong2(a0, a1);
                *(ulonglong2*)&hb2[1][row][cg + 2] = make_ulonglong2(a2, a3);
            }
        }
    }
    __syncthreads();

    // ---- vertical 11-tap conv (packed) + SSIM: 32 cols x 8 groups of 4 rows
    float lsum = 0.0f;
    {
        DECLARE_W2
        const int c = tid & 31;
        const int rb = (tid >> 5) << 2;

        u64 accA[4], accB[4];
        {
            u64 winA[14], winB[14];
            #pragma unroll
            for (int k = 0; k < 14; k++) {
                winA[k] = hb2[0][rb + k][c];
                winB[k] = hb2[1][rb + k][c];
            }
            #pragma unroll
            for (int j = 0; j < 4; j++) { accA[j] = 0; accB[j] = 0; }
            #pragma unroll
            for (int k = 0; k < 11; k++) {
                #pragma unroll
                for (int j = 0; j < 4; j++) {
                    accA[j] = ffma2(winA[k + j], W2[k], accA[j]);
                    accB[j] = ffma2(winB[k + j], W2[k], accB[j]);
                }
            }
        }

        const float C1 = 1e-4f, C2 = 9e-4f;
        #pragma unroll
        for (int j = 0; j < 4; j++) {
            int orow = r0 + rb + j;
            int ocol = c0 + c;
            if (orow < OV && ocol < OV) {
                float m1, m2, bsv, bptv;
                upk2(accA[j], m1, m2);
                upk2(accB[j], bsv, bptv);
                float m1s = m1 * m1, m2s = m2 * m2, m12 = m1 * m2;
                float musum = m1s + m2s;
                float sigsum = bsv - musum;           // sigma1^2 + sigma2^2
                float s12 = bptv - m12;               // sigma12
                float num = (2.0f * m12 + C1) * (2.0f * s12 + C2);
                float den = (musum + C1) * (sigsum + C2) + 1e-6f;
                lsum += num / den;
            }
        }
    }

    // ---- block reduction of (msum, lsum)
    #pragma unroll
    for (int o = 16; o; o >>= 1) {
        msum += __shfl_down_sync(0xffffffffu, msum, o);
        lsum += __shfl_down_sync(0xffffffffu, lsum, o);
    }
    int lane = tid & 31, wid = tid >> 5;
    if (!lane) { ws[0][wid] = msum; ws[1][wid] = lsum; }
    __syncthreads();
    if (wid == 0) {
        msum = (lane < 8) ? ws[0][lane] : 0.0f;
        lsum = (lane < 8) ? ws[1][lane] : 0.0f;
        #pragma unroll
        for (int o = 4; o; o >>= 1) {
            msum += __shfl_down_sync(0xffffffffu, msum, o);
            lsum += __shfl_down_sync(0xffffffffu, lsum, o);
        }
        if (!lane) {
            atomicAdd(&g_accum[0], (double)msum);
            atomicAdd(&g_accum[1], (double)lsum);
            __threadfence();
            unsigned done = atomicAdd(&g_count, 1u);
            if (done == NBLOCKS - 1) {
                // all blocks' fenced atomics are visible; read via atomic RMW
                double a0 = atomicAdd(&g_accum[0], 0.0);
                double a1 = atomicAdd(&g_accum[1], 0.0);
                double mse = a0 / (double)(B * H * W);
                double smean = a1 / ((double)B * OV * OV);
                out[0] = (float)(0.6 * mse + 0.4 * (1.0 - smean));
                // reset for next graph replay (replays are serialized)
                g_accum[0] = 0.0;
                g_accum[1] = 0.0;
                g_count = 0u;
            }
        }
    }
}

// ---------------------------------------------------------------------------
extern "C" void kernel_launch(void* const* d_in, const int* in_sizes, int n_in,
                              void* d_out, int out_size)
{
    const float* pred = (const float*)d_in[0];
    const float* targ = (const float*)d_in[1];

    dim3 grid((OV + TO - 1) / TO, (OV + TO - 1) / TO, B);   // 16 x 16 x 32
    fused_kernel<<<grid, 256>>>(pred, targ, (float*)d_out);
}

// round 6
// speedup vs baseline: 1.9498x; 1.1821x over previous
#include <cuda_runtime.h>

// ---------------------------------------------------------------------------
// Fully fused MSE + SSIM loss, 32x1x512x512 fp32 -> scalar. ONE kernel.
// Round-6: smem-crossbar optimization. Conflict-free strides (s2: 368B,
// hb: 528B -> all LDS/STS at the 4-wavefront minimum), interleaved (A,B)
// hconv output (LDS.128 in vconv), 64x32 output tiles with streaming
// 8-output vconv, MSE fused into the float4 load phase. Packed fma.rn.f32x2
// throughout (2 FMAs/slot).
// ---------------------------------------------------------------------------

#define H 512
#define W 512
#define B 32
#define OV 502            // valid output size (512 - 11 + 1)
#define TOR 64            // output tile rows
#define TOC 32            // output tile cols
#define TIR 74            // input tile rows  (TOR + 10)
#define S2S 46            // s2 row stride in u64 (368B: coeff 28 mod 32 banks)
#define HBS 33            // hb row stride in ulonglong2 (528B: coeff 4 mod 32)
#define NBLOCKS (16 * 8 * 32)

#define S2_BYTES  (TIR * S2S * 8)        // 27232
#define HB_BYTES  (TIR * HBS * 16)       // 39072
#define WS_OFF    (S2_BYTES + HB_BYTES)  // 66304
#define SMEM_SZ   (WS_OFF + 64)          // 66368

typedef unsigned long long u64;

__device__ __forceinline__ u64 pk2(float lo, float hi) {
    u64 r; asm("mov.b64 %0, {%1, %2};" : "=l"(r) : "f"(lo), "f"(hi)); return r;
}
__device__ __forceinline__ void upk2(u64 v, float& lo, float& hi) {
    asm("mov.b64 {%0, %1}, %2;" : "=f"(lo), "=f"(hi) : "l"(v));
}
__device__ __forceinline__ u64 ffma2(u64 a, u64 w, u64 c) {
    u64 d; asm("fma.rn.f32x2 %0, %1, %2, %3;" : "=l"(d) : "l"(a), "l"(w), "l"(c));
    return d;
}

// 11-tap Gaussian, sigma=1.5, normalized; symmetric -> 6 distinct values.
#define GW0 0.00102838f
#define GW1 0.00759875f
#define GW2 0.03600077f
#define GW3 0.10936080f
#define GW4 0.21300549f
#define GW5 0.26601166f
#define DECLARE_W2                                                            \
    const u64 W2[11] = {                                                      \
        pk2(GW0, GW0), pk2(GW1, GW1), pk2(GW2, GW2), pk2(GW3, GW3),           \
        pk2(GW4, GW4), pk2(GW5, GW5),                                         \
        pk2(GW4, GW4), pk2(GW3, GW3), pk2(GW2, GW2), pk2(GW1, GW1),           \
        pk2(GW0, GW0) };

__device__ double g_accum[2] = {0.0, 0.0};   // [0]=mse sum, [1]=ssim sum
__device__ unsigned int g_count = 0;

__global__ __launch_bounds__(256, 3) void fused_kernel(
    const float* __restrict__ pred, const float* __restrict__ targ,
    float* __restrict__ out)
{
    extern __shared__ __align__(16) char dsm[];
    u64 (*s2)[S2S] = (u64(*)[S2S])dsm;                       // (p,t) packed
    ulonglong2 (*hb)[HBS] = (ulonglong2(*)[HBS])(dsm + S2_BYTES); // (A,B)
    float* ws = (float*)(dsm + WS_OFF);

    const int tid = threadIdx.x;
    const int r0 = blockIdx.y * TOR;
    const int c0 = blockIdx.x * TOC;
    const float* pim = pred + (size_t)blockIdx.z * (H * W);
    const float* tim = targ + (size_t)blockIdx.z * (H * W);

    // ---- load 74x44 halo tile as float4 pairs; fuse MSE over owned 64x32.
    // Clamped rows/cols duplicate edge data; duplicates only feed outputs
    // with orow/ocol >= 502, which are masked out in the epilogue.
    float msum = 0.0f;
    for (int i = tid; i < TIR * 11; i += 256) {
        int row = i / 11, q = i - row * 11;
        int gr = min(r0 + row, H - 1);
        int gc = min(c0 + 4 * q, W - 4);
        const float4 p4 = *(const float4*)(pim + gr * W + gc);
        const float4 t4 = *(const float4*)(tim + gr * W + gc);
        if (row < TOR && q < 8) {    // owned interior pixel (tiles partition)
            float d0 = p4.x - t4.x, d1 = p4.y - t4.y;
            float d2 = p4.z - t4.z, d3 = p4.w - t4.w;
            msum = fmaf(d0, d0, msum); msum = fmaf(d1, d1, msum);
            msum = fmaf(d2, d2, msum); msum = fmaf(d3, d3, msum);
        }
        *(ulonglong2*)&s2[row][4 * q + 0] =
            make_ulonglong2(pk2(p4.x, t4.x), pk2(p4.y, t4.y));
        *(ulonglong2*)&s2[row][4 * q + 2] =
            make_ulonglong2(pk2(p4.z, t4.z), pk2(p4.w, t4.w));
    }
    __syncthreads();

    // ---- horizontal 11-tap conv, 2 packed chains. Column-major task map:
    // warp lanes = consecutive rows (conflict-free with S2S/HBS strides).
    {
        DECLARE_W2
        for (int t = tid; t < TIR * 8; t += 256) {
            int row = t % TIR;
            int cg = (t / TIR) * 4;

            u64 win[14];
            #pragma unroll
            for (int q = 0; q < 7; q++) {
                ulonglong2 v = *(const ulonglong2*)&s2[row][cg + 2 * q];
                win[2 * q + 0] = v.x;
                win[2 * q + 1] = v.y;
            }
            u64 a0 = 0, a1 = 0, a2 = 0, a3 = 0;
            #pragma unroll
            for (int k = 0; k < 11; k++) {
                a0 = ffma2(win[k + 0], W2[k], a0);
                a1 = ffma2(win[k + 1], W2[k], a1);
                a2 = ffma2(win[k + 2], W2[k], a2);
                a3 = ffma2(win[k + 3], W2[k], a3);
            }
            #pragma unroll
            for (int k = 0; k < 14; k++) {   // (p,t) -> (p^2+t^2, p*t)
                float p, tt;
                upk2(win[k], p, tt);
                win[k] = pk2(fmaf(p, p, tt * tt), p * tt);
            }
            u64 b0 = 0, b1 = 0, b2 = 0, b3 = 0;
            #pragma unroll
            for (int k = 0; k < 11; k++) {
                b0 = ffma2(win[k + 0], W2[k], b0);
                b1 = ffma2(win[k + 1], W2[k], b1);
                b2 = ffma2(win[k + 2], W2[k], b2);
                b3 = ffma2(win[k + 3], W2[k], b3);
            }
            hb[row][cg + 0] = make_ulonglong2(a0, b0);
            hb[row][cg + 1] = make_ulonglong2(a1, b1);
            hb[row][cg + 2] = make_ulonglong2(a2, b2);
            hb[row][cg + 3] = make_ulonglong2(a3, b3);
        }
    }
    __syncthreads();

    // ---- vertical 11-tap conv, streaming: each thread owns (col, 8 rows).
    // 18 LDS.128, 32 packed accumulators, then SSIM epilogue.
    float lsum = 0.0f;
    {
        DECLARE_W2
        const int c = tid & 31;
        const int rb = (tid >> 5) << 3;        // 0,8,...,56

        u64 accA[8], accB[8];
        #pragma unroll
        for (int j = 0; j < 8; j++) { accA[j] = 0; accB[j] = 0; }

        #pragma unroll
        for (int k = 0; k < 18; k++) {
            ulonglong2 v = hb[rb + k][c];
            #pragma unroll
            for (int j = 0; j < 8; j++) {
                if (k - j >= 0 && k - j <= 10) {
                    accA[j] = ffma2(v.x, W2[k - j], accA[j]);
                    accB[j] = ffma2(v.y, W2[k - j], accB[j]);
                }
            }
        }

        const float C1 = 1e-4f, C2 = 9e-4f;
        const int ocol = c0 + c;
        #pragma unroll
        for (int j = 0; j < 8; j++) {
            int orow = r0 + rb + j;
            if (orow < OV && ocol < OV) {
                float m1, m2, bsv, bptv;
                upk2(accA[j], m1, m2);
                upk2(accB[j], bsv, bptv);
                float m1s = m1 * m1, m2s = m2 * m2, m12 = m1 * m2;
                float musum = m1s + m2s;
                float sigsum = bsv - musum;           // sigma1^2 + sigma2^2
                float s12 = bptv - m12;               // sigma12
                float num = (2.0f * m12 + C1) * (2.0f * s12 + C2);
                float den = (musum + C1) * (sigsum + C2) + 1e-6f;
                lsum += num / den;
            }
        }
    }

    // ---- block reduction of (msum, lsum)
    #pragma unroll
    for (int o = 16; o; o >>= 1) {
        msum += __shfl_down_sync(0xffffffffu, msum, o);
        lsum += __shfl_down_sync(0xffffffffu, lsum, o);
    }
    int lane = tid & 31, wid = tid >> 5;
    if (!lane) { ws[wid] = msum; ws[8 + wid] = lsum; }
    __syncthreads();
    if (wid == 0) {
        msum = (lane < 8) ? ws[lane] : 0.0f;
        lsum = (lane < 8) ? ws[8 + lane] : 0.0f;
        #pragma unroll
        for (int o = 4; o; o >>= 1) {
            msum += __shfl_down_sync(0xffffffffu, msum, o);
            lsum += __shfl_down_sync(0xffffffffu, lsum, o);
        }
        if (!lane) {
            atomicAdd(&g_accum[0], (double)msum);
            atomicAdd(&g_accum[1], (double)lsum);
            __threadfence();
            unsigned done = atomicAdd(&g_count, 1u);
            if (done == NBLOCKS - 1) {
                // all blocks' fenced atomics visible; read via atomic RMW
                double a0 = atomicAdd(&g_accum[0], 0.0);
                double a1 = atomicAdd(&g_accum[1], 0.0);
                double mse = a0 / (double)(B * H * W);
                double smean = a1 / ((double)B * OV * OV);
                out[0] = (float)(0.6 * mse + 0.4 * (1.0 - smean));
                // reset for next graph replay (replays are serialized)
                g_accum[0] = 0.0;
                g_accum[1] = 0.0;
                g_count = 0u;
            }
        }
    }
}

// ---------------------------------------------------------------------------
extern "C" void kernel_launch(void* const* d_in, const int* in_sizes, int n_in,
                              void* d_out, int out_size)
{
    const float* pred = (const float*)d_in[0];
    const float* targ = (const float*)d_in[1];

    cudaFuncSetAttribute(fused_kernel,
                         cudaFuncAttributeMaxDynamicSharedMemorySize, SMEM_SZ);

    dim3 grid(16, 8, B);   // 16 col-tiles x 8 row-tiles x 32 images
    fused_kernel<<<grid, 256, SMEM_SZ>>>(pred, targ, (float*)d_out);
}

// round 7
// speedup vs baseline: 2.0345x; 1.0435x over previous
#include <cuda_runtime.h>

// ---------------------------------------------------------------------------
// Fully fused MSE + SSIM loss, 32x1x512x512 fp32 -> scalar. ONE kernel.
// Round-7: occupancy push. 48x32 tile shrinks smem 66.4->52KB = 4 CTAs/SM
// (was 3); __launch_bounds__(256,4) caps regs to fit the 64K reg file.
// Keeps round-6 conflict-free strides, packed fma.rn.f32x2, fused MSE,
// last-block epilogue.
// ---------------------------------------------------------------------------

#define H 512
#define W 512
#define B 32
#define OV 502            // valid output size (512 - 11 + 1)
#define TOR 48            // output tile rows
#define TOC 32            // output tile cols
#define TIR 58            // input tile rows  (TOR + 10)
#define S2S 46            // s2 row stride in u64 (368B: coeff 28 mod 32 banks)
#define HBS 33            // hb row stride in ulonglong2 (528B: coeff 4 mod 32)
#define NTROW 11          // row tiles (11*48 = 528 >= 502)
#define NBLOCKS (16 * NTROW * 32)

#define S2_BYTES  (TIR * S2S * 8)        // 21344
#define HB_BYTES  (TIR * HBS * 16)       // 30624
#define WS_OFF    (S2_BYTES + HB_BYTES)  // 51968
#define SMEM_SZ   (WS_OFF + 64)          // 52032  -> 4 CTAs/SM

typedef unsigned long long u64;

__device__ __forceinline__ u64 pk2(float lo, float hi) {
    u64 r; asm("mov.b64 %0, {%1, %2};" : "=l"(r) : "f"(lo), "f"(hi)); return r;
}
__device__ __forceinline__ void upk2(u64 v, float& lo, float& hi) {
    asm("mov.b64 {%0, %1}, %2;" : "=f"(lo), "=f"(hi) : "l"(v));
}
__device__ __forceinline__ u64 ffma2(u64 a, u64 w, u64 c) {
    u64 d; asm("fma.rn.f32x2 %0, %1, %2, %3;" : "=l"(d) : "l"(a), "l"(w), "l"(c));
    return d;
}

// 11-tap Gaussian, sigma=1.5, normalized; symmetric -> 6 distinct values.
#define GW0 0.00102838f
#define GW1 0.00759875f
#define GW2 0.03600077f
#define GW3 0.10936080f
#define GW4 0.21300549f
#define GW5 0.26601166f
#define DECLARE_W2                                                            \
    const u64 W2[11] = {                                                      \
        pk2(GW0, GW0), pk2(GW1, GW1), pk2(GW2, GW2), pk2(GW3, GW3),           \
        pk2(GW4, GW4), pk2(GW5, GW5),                                         \
        pk2(GW4, GW4), pk2(GW3, GW3), pk2(GW2, GW2), pk2(GW1, GW1),           \
        pk2(GW0, GW0) };

__device__ double g_accum[2] = {0.0, 0.0};   // [0]=mse sum, [1]=ssim sum
__device__ unsigned int g_count = 0;

__global__ __launch_bounds__(256, 4) void fused_kernel(
    const float* __restrict__ pred, const float* __restrict__ targ,
    float* __restrict__ out)
{
    extern __shared__ __align__(16) char dsm[];
    u64 (*s2)[S2S] = (u64(*)[S2S])dsm;                            // (p,t)
    ulonglong2 (*hb)[HBS] = (ulonglong2(*)[HBS])(dsm + S2_BYTES); // (A,B)
    float* ws = (float*)(dsm + WS_OFF);

    const int tid = threadIdx.x;
    const int r0 = blockIdx.y * TOR;
    const int c0 = blockIdx.x * TOC;
    const float* pim = pred + (size_t)blockIdx.z * (H * W);
    const float* tim = targ + (size_t)blockIdx.z * (H * W);

    // ---- load 58x44 halo tile as float4 pairs; fuse MSE over owned pixels.
    // Ownership: row < TOR, q < 8, and r0+row < H (bottom tile overlaps the
    // image edge since 11*48 > 512; clamped duplicates must not count).
    float msum = 0.0f;
    for (int i = tid; i < TIR * 11; i += 256) {
        int row = i / 11, q = i - row * 11;
        int gr = min(r0 + row, H - 1);
        int gc = min(c0 + 4 * q, W - 4);
        const float4 p4 = *(const float4*)(pim + gr * W + gc);
        const float4 t4 = *(const float4*)(tim + gr * W + gc);
        if (row < TOR && q < 8 && (r0 + row) < H) {
            float d0 = p4.x - t4.x, d1 = p4.y - t4.y;
            float d2 = p4.z - t4.z, d3 = p4.w - t4.w;
            msum = fmaf(d0, d0, msum); msum = fmaf(d1, d1, msum);
            msum = fmaf(d2, d2, msum); msum = fmaf(d3, d3, msum);
        }
        *(ulonglong2*)&s2[row][4 * q + 0] =
            make_ulonglong2(pk2(p4.x, t4.x), pk2(p4.y, t4.y));
        *(ulonglong2*)&s2[row][4 * q + 2] =
            make_ulonglong2(pk2(p4.z, t4.z), pk2(p4.w, t4.w));
    }
    __syncthreads();

    // ---- horizontal 11-tap conv, 2 packed chains. Column-major task map:
    // warp lanes = consecutive rows (conflict-free with S2S/HBS strides).
    {
        DECLARE_W2
        for (int t = tid; t < TIR * 8; t += 256) {
            int row = t % TIR;
            int cg = (t / TIR) * 4;

            u64 win[14];
            #pragma unroll
            for (int q = 0; q < 7; q++) {
                ulonglong2 v = *(const ulonglong2*)&s2[row][cg + 2 * q];
                win[2 * q + 0] = v.x;
                win[2 * q + 1] = v.y;
            }
            u64 a0 = 0, a1 = 0, a2 = 0, a3 = 0;
            #pragma unroll
            for (int k = 0; k < 11; k++) {
                a0 = ffma2(win[k + 0], W2[k], a0);
                a1 = ffma2(win[k + 1], W2[k], a1);
                a2 = ffma2(win[k + 2], W2[k], a2);
                a3 = ffma2(win[k + 3], W2[k], a3);
            }
            #pragma unroll
            for (int k = 0; k < 14; k++) {   // (p,t) -> (p^2+t^2, p*t)
                float p, tt;
                upk2(win[k], p, tt);
                win[k] = pk2(fmaf(p, p, tt * tt), p * tt);
            }
            u64 b0 = 0, b1 = 0, b2 = 0, b3 = 0;
            #pragma unroll
            for (int k = 0; k < 11; k++) {
                b0 = ffma2(win[k + 0], W2[k], b0);
                b1 = ffma2(win[k + 1], W2[k], b1);
                b2 = ffma2(win[k + 2], W2[k], b2);
                b3 = ffma2(win[k + 3], W2[k], b3);
            }
            hb[row][cg + 0] = make_ulonglong2(a0, b0);
            hb[row][cg + 1] = make_ulonglong2(a1, b1);
            hb[row][cg + 2] = make_ulonglong2(a2, b2);
            hb[row][cg + 3] = make_ulonglong2(a3, b3);
        }
    }
    __syncthreads();

    // ---- vertical 11-tap conv, streaming: each thread owns (col, 6 rows).
    // 16 LDS.128, 24 packed accumulators, then SSIM epilogue.
    float lsum = 0.0f;
    {
        DECLARE_W2
        const int c = tid & 31;
        const int rb = (tid >> 5) * 6;         // 0,6,...,42

        u64 accA[6], accB[6];
        #pragma unroll
        for (int j = 0; j < 6; j++) { accA[j] = 0; accB[j] = 0; }

        #pragma unroll
        for (int k = 0; k < 16; k++) {
            ulonglong2 v = hb[rb + k][c];
            #pragma unroll
            for (int j = 0; j < 6; j++) {
                if (k - j >= 0 && k - j <= 10) {
                    accA[j] = ffma2(v.x, W2[k - j], accA[j]);
                    accB[j] = ffma2(v.y, W2[k - j], accB[j]);
                }
            }
        }

        const float C1 = 1e-4f, C2 = 9e-4f;
        const int ocol = c0 + c;
        #pragma unroll
        for (int j = 0; j < 6; j++) {
            int orow = r0 + rb + j;
            if (orow < OV && ocol < OV) {
                float m1, m2, bsv, bptv;
                upk2(accA[j], m1, m2);
                upk2(accB[j], bsv, bptv);
                float m1s = m1 * m1, m2s = m2 * m2, m12 = m1 * m2;
                float musum = m1s + m2s;
                float sigsum = bsv - musum;           // sigma1^2 + sigma2^2
                float s12 = bptv - m12;               // sigma12
                float num = (2.0f * m12 + C1) * (2.0f * s12 + C2);
                float den = (musum + C1) * (sigsum + C2) + 1e-6f;
                lsum += num / den;
            }
        }
    }

    // ---- block reduction of (msum, lsum)
    #pragma unroll
    for (int o = 16; o; o >>= 1) {
        msum += __shfl_down_sync(0xffffffffu, msum, o);
        lsum += __shfl_down_sync(0xffffffffu, lsum, o);
    }
    int lane = tid & 31, wid = tid >> 5;
    if (!lane) { ws[wid] = msum; ws[8 + wid] = lsum; }
    __syncthreads();
    if (wid == 0) {
        msum = (lane < 8) ? ws[lane] : 0.0f;
        lsum = (lane < 8) ? ws[8 + lane] : 0.0f;
        #pragma unroll
        for (int o = 4; o; o >>= 1) {
            msum += __shfl_down_sync(0xffffffffu, msum, o);
            lsum += __shfl_down_sync(0xffffffffu, lsum, o);
        }
        if (!lane) {
            atomicAdd(&g_accum[0], (double)msum);
            atomicAdd(&g_accum[1], (double)lsum);
            __threadfence();
            unsigned done = atomicAdd(&g_count, 1u);
            if (done == NBLOCKS - 1) {
                // all blocks' fenced atomics visible; read via atomic RMW
                double a0 = atomicAdd(&g_accum[0], 0.0);
                double a1 = atomicAdd(&g_accum[1], 0.0);
                double mse = a0 / (double)(B * H * W);
                double smean = a1 / ((double)B * OV * OV);
                out[0] = (float)(0.6 * mse + 0.4 * (1.0 - smean));
                // reset for next graph replay (replays are serialized)
                g_accum[0] = 0.0;
                g_accum[1] = 0.0;
                g_count = 0u;
            }
        }
    }
}

// ---------------------------------------------------------------------------
extern "C" void kernel_launch(void* const* d_in, const int* in_sizes, int n_in,
                              void* d_out, int out_size)
{
    const float* pred = (const float*)d_in[0];
    const float* targ = (const float*)d_in[1];

    cudaFuncSetAttribute(fused_kernel,
                         cudaFuncAttributeMaxDynamicSharedMemorySize, SMEM_SZ);

    dim3 grid(16, NTROW, B);   // 16 col-tiles x 11 row-tiles x 32 images
    fused_kernel<<<grid, 256, SMEM_SZ>>>(pred, targ, (float*)d_out);
}

// round 8
// speedup vs baseline: 2.1430x; 1.0533x over previous
#include <cuda_runtime.h>

// ---------------------------------------------------------------------------
// Fully fused MSE + SSIM loss, 32x1x512x512 fp32 -> scalar. ONE kernel.
// Round-8: hconv reads its 14-px windows DIRECTLY from gmem (coalesced via
// row-major task map), eliminating the s2 input tile, its STS/LDS traffic,
// and one barrier. hb stored with permuted columns (cg + 8j) to keep STS.128
// at the 4-wavefront minimum. smem 52->30.7KB; launch_bounds(256,5).
// Packed fma.rn.f32x2 throughout; MSE fused into the window loads;
// last-block epilogue.
// ---------------------------------------------------------------------------

#define H 512
#define W 512
#define B 32
#define OV 502            // valid output size (512 - 11 + 1)
#define TOR 48            // output tile rows
#define TOC 32            // output tile cols
#define TIR 58            // input tile rows  (TOR + 10)
#define HBS 33            // hb row stride in ulonglong2 (528B: coeff 4 mod 32)
#define NTROW 11          // row tiles (11*48 = 528 >= 502)
#define NBLOCKS (16 * NTROW * 32)

#define HB_BYTES  (TIR * HBS * 16)       // 30624
#define SMEM_SZ   (HB_BYTES + 64)        // 30688

typedef unsigned long long u64;

__device__ __forceinline__ u64 pk2(float lo, float hi) {
    u64 r; asm("mov.b64 %0, {%1, %2};" : "=l"(r) : "f"(lo), "f"(hi)); return r;
}
__device__ __forceinline__ void upk2(u64 v, float& lo, float& hi) {
    asm("mov.b64 {%0, %1}, %2;" : "=f"(lo), "=f"(hi) : "l"(v));
}
__device__ __forceinline__ u64 ffma2(u64 a, u64 w, u64 c) {
    u64 d; asm("fma.rn.f32x2 %0, %1, %2, %3;" : "=l"(d) : "l"(a), "l"(w), "l"(c));
    return d;
}

// 11-tap Gaussian, sigma=1.5, normalized; symmetric -> 6 distinct values.
#define GW0 0.00102838f
#define GW1 0.00759875f
#define GW2 0.03600077f
#define GW3 0.10936080f
#define GW4 0.21300549f
#define GW5 0.26601166f
#define DECLARE_W2                                                            \
    const u64 W2[11] = {                                                      \
        pk2(GW0, GW0), pk2(GW1, GW1), pk2(GW2, GW2), pk2(GW3, GW3),           \
        pk2(GW4, GW4), pk2(GW5, GW5),                                         \
        pk2(GW4, GW4), pk2(GW3, GW3), pk2(GW2, GW2), pk2(GW1, GW1),           \
        pk2(GW0, GW0) };

__device__ double g_accum[2] = {0.0, 0.0};   // [0]=mse sum, [1]=ssim sum
__device__ unsigned int g_count = 0;

__global__ __launch_bounds__(256, 5) void fused_kernel(
    const float* __restrict__ pred, const float* __restrict__ targ,
    float* __restrict__ out)
{
    extern __shared__ __align__(16) char dsm[];
    ulonglong2 (*hb)[HBS] = (ulonglong2(*)[HBS])dsm;   // (A,B) packed pairs
    float* ws = (float*)(dsm + HB_BYTES);

    const int tid = threadIdx.x;
    const int r0 = blockIdx.y * TOR;
    const int c0 = blockIdx.x * TOC;
    const float* pim = pred + (size_t)blockIdx.z * (H * W);
    const float* tim = targ + (size_t)blockIdx.z * (H * W);

    float msum = 0.0f;

    // ---- fused gmem-load + horizontal conv. Row-major tasks: 58 rows x
    // 8 col-groups; warp lanes = (cg, row) -> coalesced LDG, conflict-free
    // STS with the cg+8j column permutation.
    {
        DECLARE_W2
        for (int t = tid; t < TIR * 8; t += 256) {
            int row = t >> 3, cg = t & 7;
            int gr = min(r0 + row, H - 1);
            const float* prow = pim + gr * W;
            const float* trow = tim + gr * W;
            const int cbase = c0 + 4 * cg;

            float4 P[4], T[4];
            #pragma unroll
            for (int j = 0; j < 4; j++) {
                int gc = min(cbase + 4 * j, W - 4);   // clamp dups feed only
                P[j] = *(const float4*)(prow + gc);   // invalid outputs
                T[j] = *(const float4*)(trow + gc);
            }

            // MSE: this task owns pixels (gr, cbase..cbase+3) exactly once
            // (clamped bottom rows excluded via r0+row < H).
            if (row < TOR && (r0 + row) < H) {
                float d0 = P[0].x - T[0].x, d1 = P[0].y - T[0].y;
                float d2 = P[0].z - T[0].z, d3 = P[0].w - T[0].w;
                msum = fmaf(d0, d0, msum); msum = fmaf(d1, d1, msum);
                msum = fmaf(d2, d2, msum); msum = fmaf(d3, d3, msum);
            }

            // pack (p,t) window; P/T die here
            u64 win[14];
            #pragma unroll
            for (int j = 0; j < 4; j++) {
                if (4 * j + 0 < 14) win[4 * j + 0] = pk2(P[j].x, T[j].x);
                if (4 * j + 1 < 14) win[4 * j + 1] = pk2(P[j].y, T[j].y);
                if (4 * j + 2 < 14) win[4 * j + 2] = pk2(P[j].z, T[j].z);
                if (4 * j + 3 < 14) win[4 * j + 3] = pk2(P[j].w, T[j].w);
            }

            u64 a0 = 0, a1 = 0, a2 = 0, a3 = 0;
            #pragma unroll
            for (int k = 0; k < 11; k++) {
                a0 = ffma2(win[k + 0], W2[k], a0);
                a1 = ffma2(win[k + 1], W2[k], a1);
                a2 = ffma2(win[k + 2], W2[k], a2);
                a3 = ffma2(win[k + 3], W2[k], a3);
            }
            #pragma unroll
            for (int k = 0; k < 14; k++) {   // (p,t) -> (p^2+t^2, p*t)
                float p, tt;
                upk2(win[k], p, tt);
                win[k] = pk2(fmaf(p, p, tt * tt), p * tt);
            }
            u64 b0 = 0, b1 = 0, b2 = 0, b3 = 0;
            #pragma unroll
            for (int k = 0; k < 11; k++) {
                b0 = ffma2(win[k + 0], W2[k], b0);
                b1 = ffma2(win[k + 1], W2[k], b1);
                b2 = ffma2(win[k + 2], W2[k], b2);
                b3 = ffma2(win[k + 3], W2[k], b3);
            }
            // permuted store: storage col = cg + 8j holds actual col 4cg+j.
            // Quarter-warp (8 lanes, same row, cg 0..7) writes 128B
            // contiguous -> 4-wavefront STS.128.
            hb[row][cg +  0] = make_ulonglong2(a0, b0);
            hb[row][cg +  8] = make_ulonglong2(a1, b1);
            hb[row][cg + 16] = make_ulonglong2(a2, b2);
            hb[row][cg + 24] = make_ulonglong2(a3, b3);
        }
    }
    __syncthreads();

    // ---- vertical 11-tap conv, streaming: each thread owns (storage col,
    // 6 rows). 16 LDS.128, 24 packed accumulators, then SSIM epilogue.
    float lsum = 0.0f;
    {
        DECLARE_W2
        const int c = tid & 31;                    // storage column
        const int acol = 4 * (c & 7) + (c >> 3);   // actual column
        const int rb = (tid >> 5) * 6;             // 0,6,...,42

        u64 accA[6], accB[6];
        #pragma unroll
        for (int j = 0; j < 6; j++) { accA[j] = 0; accB[j] = 0; }

        #pragma unroll
        for (int k = 0; k < 16; k++) {
            ulonglong2 v = hb[rb + k][c];
            #pragma unroll
            for (int j = 0; j < 6; j++) {
                if (k - j >= 0 && k - j <= 10) {
                    accA[j] = ffma2(v.x, W2[k - j], accA[j]);
                    accB[j] = ffma2(v.y, W2[k - j], accB[j]);
                }
            }
        }

        const float C1 = 1e-4f, C2 = 9e-4f;
        const int ocol = c0 + acol;
        #pragma unroll
        for (int j = 0; j < 6; j++) {
            int orow = r0 + rb + j;
            if (orow < OV && ocol < OV) {
                float m1, m2, bsv, bptv;
                upk2(accA[j], m1, m2);
                upk2(accB[j], bsv, bptv);
                float m1s = m1 * m1, m2s = m2 * m2, m12 = m1 * m2;
                float musum = m1s + m2s;
                float sigsum = bsv - musum;           // sigma1^2 + sigma2^2
                float s12 = bptv - m12;               // sigma12
                float num = (2.0f * m12 + C1) * (2.0f * s12 + C2);
                float den = (musum + C1) * (sigsum + C2) + 1e-6f;
                lsum += num / den;
            }
        }
    }

    // ---- block reduction of (msum, lsum)
    #pragma unroll
    for (int o = 16; o; o >>= 1) {
        msum += __shfl_down_sync(0xffffffffu, msum, o);
        lsum += __shfl_down_sync(0xffffffffu, lsum, o);
    }
    int lane = tid & 31, wid = tid >> 5;
    if (!lane) { ws[wid] = msum; ws[8 + wid] = lsum; }
    __syncthreads();
    if (wid == 0) {
        msum = (lane < 8) ? ws[lane] : 0.0f;
        lsum = (lane < 8) ? ws[8 + lane] : 0.0f;
        #pragma unroll
        for (int o = 4; o; o >>= 1) {
            msum += __shfl_down_sync(0xffffffffu, msum, o);
            lsum += __shfl_down_sync(0xffffffffu, lsum, o);
        }
        if (!lane) {
            atomicAdd(&g_accum[0], (double)msum);
            atomicAdd(&g_accum[1], (double)lsum);
            __threadfence();
            unsigned done = atomicAdd(&g_count, 1u);
            if (done == NBLOCKS - 1) {
                // all blocks' fenced atomics visible; read via atomic RMW
                double a0 = atomicAdd(&g_accum[0], 0.0);
                double a1 = atomicAdd(&g_accum[1], 0.0);
                double mse = a0 / (double)(B * H * W);
                double smean = a1 / ((double)B * OV * OV);
                out[0] = (float)(0.6 * mse + 0.4 * (1.0 - smean));
                // reset for next graph replay (replays are serialized)
                g_accum[0] = 0.0;
                g_accum[1] = 0.0;
                g_count = 0u;
            }
        }
    }
}

// ---------------------------------------------------------------------------
extern "C" void kernel_launch(void* const* d_in, const int* in_sizes, int n_in,
                              void* d_out, int out_size)
{
    const float* pred = (const float*)d_in[0];
    const float* targ = (const float*)d_in[1];

    cudaFuncSetAttribute(fused_kernel,
                         cudaFuncAttributeMaxDynamicSharedMemorySize, SMEM_SZ);

    dim3 grid(16, NTROW, B);   // 16 col-tiles x 11 row-tiles x 32 images
    fused_kernel<<<grid, 256, SMEM_SZ>>>(pred, targ, (float*)d_out);
}